// round 2
// baseline (speedup 1.0000x reference)
#include <cuda_runtime.h>

#define F_IN  8064
#define F_OUT 5000
#define NG    32
#define NPG   32
#define TT    2500

// ---- device scratch (no allocations allowed) ----
__device__ float g_c[NG * NPG];
__device__ float g_A[NG * F_IN];
__device__ float g_S[NG * F_IN];
__device__ float g_pooled[NG * F_OUT];

// ============================================================
// K0: per-node outgoing edge-weight sums c_j, and init pooled = 32*b_rel
// ============================================================
__global__ void k_prep(const int* __restrict__ edge_index,
                       const float* __restrict__ edge_attr,
                       const float* __restrict__ b_rel, int E) {
    __shared__ float cs[NG * NPG];
    int tid = threadIdx.x;
    cs[tid] = 0.f;
    __syncthreads();
    for (int e = tid; e < E; e += 1024)
        atomicAdd(&cs[edge_index[e]], edge_attr[e]);  // src row of edge_index
    __syncthreads();
    g_c[tid] = cs[tid];
    for (int i = tid; i < NG * F_OUT; i += 1024)
        g_pooled[i] = 32.0f * b_rel[i % F_OUT];
}

// ============================================================
// K1: A[g,f] = sum_j c_j * x[g*32+j, f];  S[g,f] = sum_j x[g*32+j, f]
// grid (63, 32), 128 threads
// ============================================================
__global__ void k_reduce(const float* __restrict__ x) {
    int g = blockIdx.y;
    int f = blockIdx.x * 128 + threadIdx.x;
    __shared__ float cs[NPG];
    if (threadIdx.x < NPG) cs[threadIdx.x] = g_c[g * NPG + threadIdx.x];
    __syncthreads();
    const float* xp = x + (size_t)(g * NPG) * F_IN + f;
    float a = 0.f, s = 0.f;
#pragma unroll
    for (int j = 0; j < NPG; j++) {
        float v = xp[(size_t)j * F_IN];
        a = fmaf(cs[j], v, a);
        s += v;
    }
    g_A[g * F_IN + f] = a;
    g_S[g * F_IN + f] = s;
}

// ============================================================
// K2: pooled[g,o] += sum_k A[g,k]*W_rel[o,k] + S[g,k]*W_root[o,k]
// grid (20 o-tiles of 256, 21 k-splits of 384), 128 threads, 2 o per thread
// ============================================================
#define KSPLIT 21
#define KRANGE 384
#define KT     128

__global__ void __launch_bounds__(128) k_gemm(const float* __restrict__ Wrel,
                                              const float* __restrict__ Wroot) {
    __shared__ float sA[32][KT];
    __shared__ float sS[32][KT];
    int tid = threadIdx.x;
    int oa = blockIdx.x * 256 + tid;          // always < 5000
    int ob = oa + 128;
    bool vb = (ob < F_OUT);
    int obc = vb ? ob : oa;
    int k0 = blockIdx.y * KRANGE;

    float acc0[32], acc1[32];
#pragma unroll
    for (int g = 0; g < 32; g++) { acc0[g] = 0.f; acc1[g] = 0.f; }

    for (int ch = 0; ch < KRANGE / KT; ch++) {
        int kc = k0 + ch * KT;
        __syncthreads();
        for (int idx = tid; idx < 32 * KT; idx += 128) {
            int r = idx / KT, c = idx % KT;
            sA[r][c] = g_A[r * F_IN + kc + c];
            sS[r][c] = g_S[r * F_IN + kc + c];
        }
        __syncthreads();
        const float4* wra = (const float4*)(Wrel  + (size_t)oa  * F_IN + kc);
        const float4* wrb = (const float4*)(Wrel  + (size_t)obc * F_IN + kc);
        const float4* woa = (const float4*)(Wroot + (size_t)oa  * F_IN + kc);
        const float4* wob = (const float4*)(Wroot + (size_t)obc * F_IN + kc);
#pragma unroll 1
        for (int q = 0; q < KT / 4; q++) {
            float4 ra = wra[q], rb = wrb[q], ta = woa[q], tb = wob[q];
#pragma unroll
            for (int c = 0; c < 4; c++) {
                int k = q * 4 + c;
                float wr0 = (&ra.x)[c], wr1 = (&rb.x)[c];
                float wo0 = (&ta.x)[c], wo1 = (&tb.x)[c];
#pragma unroll
                for (int g = 0; g < 32; g++) {
                    float av = sA[g][k], sv = sS[g][k];
                    acc0[g] = fmaf(av, wr0, fmaf(sv, wo0, acc0[g]));
                    acc1[g] = fmaf(av, wr1, fmaf(sv, wo1, acc1[g]));
                }
            }
        }
    }
#pragma unroll
    for (int g = 0; g < 32; g++) {
        atomicAdd(&g_pooled[g * F_OUT + oa], acc0[g]);
        if (vb) atomicAdd(&g_pooled[g * F_OUT + ob], acc1[g]);
    }
}

// ============================================================
// K3: two BiLSTM layers (HID=3) + fused final MLP dot. One block per graph.
// Lane 0 = forward dir, lane 1 = backward dir; all state in registers.
// smem: seq[5000] | out0[2500*8 padded] | wmlp[15000]  = 160000 B dynamic
// ============================================================
__device__ __forceinline__ float sigm(float x) {
    return __fdividef(1.f, 1.f + __expf(-x));
}
__device__ __forceinline__ float tanhp(float x) {
    return fmaf(2.f, __fdividef(1.f, 1.f + __expf(-2.f * x)), -1.f);
}

__global__ void __launch_bounds__(128) k_lstm(
    const float* __restrict__ wih0,  const float* __restrict__ whh0,
    const float* __restrict__ bih0,  const float* __restrict__ bhh0,
    const float* __restrict__ wih0r, const float* __restrict__ whh0r,
    const float* __restrict__ bih0r, const float* __restrict__ bhh0r,
    const float* __restrict__ wih1,  const float* __restrict__ whh1,
    const float* __restrict__ bih1,  const float* __restrict__ bhh1,
    const float* __restrict__ wih1r, const float* __restrict__ whh1r,
    const float* __restrict__ bih1r, const float* __restrict__ bhh1r,
    const float* __restrict__ wmlp,  const float* __restrict__ bmlp,
    float* __restrict__ out)
{
    extern __shared__ float sm[];
    float* seq = sm;              // 5000
    float* o0  = sm + 5000;       // 2500*8
    float* wm  = sm + 25000;      // 15000
    int b = blockIdx.x, tid = threadIdx.x;

    for (int i = tid; i < F_OUT; i += 128) seq[i] = g_pooled[b * F_OUT + i];
    for (int i = tid; i < 15000; i += 128) wm[i] = wmlp[i];
    __syncthreads();

    // ---------- Phase A: layer 0 (both directions) ----------
    if (tid < 2) {
        int d = tid;
        const float* WIH = d ? wih0r : wih0;
        const float* WHH = d ? whh0r : whh0;
        const float* BI  = d ? bih0r : bih0;
        const float* BH  = d ? bhh0r : bhh0;
        float wih[24], whh[36], bs[12];
#pragma unroll
        for (int i = 0; i < 24; i++) wih[i] = WIH[i];
#pragma unroll
        for (int i = 0; i < 36; i++) whh[i] = WHH[i];
#pragma unroll
        for (int i = 0; i < 12; i++) bs[i] = BI[i] + BH[i];

        float h0 = 0, h1 = 0, h2 = 0, c0 = 0, c1 = 0, c2 = 0;
        int t = d ? (TT - 1) : 0;
        float x0 = seq[2 * t], x1 = seq[2 * t + 1];
        for (int it = 0; it < TT; it++) {
            int tn = d ? (t - 1) : (t + 1);
            int tc = min(max(tn, 0), TT - 1);
            float nx0 = seq[2 * tc], nx1 = seq[2 * tc + 1];   // prefetch

            float gv[12];
#pragma unroll
            for (int k = 0; k < 12; k++)
                gv[k] = fmaf(x1, wih[2 * k + 1], fmaf(x0, wih[2 * k], bs[k]));
#pragma unroll
            for (int k = 0; k < 12; k++)
                gv[k] = fmaf(h2, whh[3 * k + 2],
                        fmaf(h1, whh[3 * k + 1], fmaf(h0, whh[3 * k], gv[k])));

            float nc0 = fmaf(sigm(gv[3]), c0, sigm(gv[0]) * tanhp(gv[6]));
            float nc1 = fmaf(sigm(gv[4]), c1, sigm(gv[1]) * tanhp(gv[7]));
            float nc2 = fmaf(sigm(gv[5]), c2, sigm(gv[2]) * tanhp(gv[8]));
            h0 = sigm(gv[9])  * tanhp(nc0);
            h1 = sigm(gv[10]) * tanhp(nc1);
            h2 = sigm(gv[11]) * tanhp(nc2);
            c0 = nc0; c1 = nc1; c2 = nc2;

            float* op = o0 + t * 8 + d * 3;
            op[0] = h0; op[1] = h1; op[2] = h2;

            t = tn; x0 = nx0; x1 = nx1;
        }
    }
    __syncthreads();

    // ---------- Phase B: layer 1 (both directions) + fused MLP dot ----------
    if (tid < 2) {
        int d = tid;
        const float* WIH = d ? wih1r : wih1;
        const float* WHH = d ? whh1r : whh1;
        const float* BI  = d ? bih1r : bih1;
        const float* BH  = d ? bhh1r : bhh1;
        float wih[72], whh[36], bs[12];
#pragma unroll
        for (int i = 0; i < 72; i++) wih[i] = WIH[i];
#pragma unroll
        for (int i = 0; i < 36; i++) whh[i] = WHH[i];
#pragma unroll
        for (int i = 0; i < 12; i++) bs[i] = BI[i] + BH[i];

        float h0 = 0, h1 = 0, h2 = 0, c0 = 0, c1 = 0, c2 = 0, acc = 0.f;
        int t = d ? (TT - 1) : 0;
        float4 va = *(const float4*)(o0 + t * 8);
        float2 v2 = *(const float2*)(o0 + t * 8 + 4);
        float w0 = wm[t * 6 + 3 * d], w1 = wm[t * 6 + 3 * d + 1], w2 = wm[t * 6 + 3 * d + 2];

        for (int it = 0; it < TT; it++) {
            int tn = d ? (t - 1) : (t + 1);
            int tc = min(max(tn, 0), TT - 1);
            float4 nva = *(const float4*)(o0 + tc * 8);        // prefetch
            float2 nv2 = *(const float2*)(o0 + tc * 8 + 4);
            float nw0 = wm[tc * 6 + 3 * d], nw1 = wm[tc * 6 + 3 * d + 1],
                  nw2 = wm[tc * 6 + 3 * d + 2];

            float v0 = va.x, v1 = va.y, v22 = va.z, v3 = va.w, v4 = v2.x, v5 = v2.y;
            float gv[12];
#pragma unroll
            for (int k = 0; k < 12; k++) {
                float gk = bs[k];
                gk = fmaf(v0, wih[6 * k + 0], gk);
                gk = fmaf(v1, wih[6 * k + 1], gk);
                gk = fmaf(v22, wih[6 * k + 2], gk);
                gk = fmaf(v3, wih[6 * k + 3], gk);
                gk = fmaf(v4, wih[6 * k + 4], gk);
                gk = fmaf(v5, wih[6 * k + 5], gk);
                gv[k] = gk;
            }
#pragma unroll
            for (int k = 0; k < 12; k++)
                gv[k] = fmaf(h2, whh[3 * k + 2],
                        fmaf(h1, whh[3 * k + 1], fmaf(h0, whh[3 * k], gv[k])));

            float nc0 = fmaf(sigm(gv[3]), c0, sigm(gv[0]) * tanhp(gv[6]));
            float nc1 = fmaf(sigm(gv[4]), c1, sigm(gv[1]) * tanhp(gv[7]));
            float nc2 = fmaf(sigm(gv[5]), c2, sigm(gv[2]) * tanhp(gv[8]));
            h0 = sigm(gv[9])  * tanhp(nc0);
            h1 = sigm(gv[10]) * tanhp(nc1);
            h2 = sigm(gv[11]) * tanhp(nc2);
            c0 = nc0; c1 = nc1; c2 = nc2;

            acc = fmaf(h0, w0, fmaf(h1, w1, fmaf(h2, w2, acc)));

            t = tn; va = nva; v2 = nv2; w0 = nw0; w1 = nw1; w2 = nw2;
        }
        float other = __shfl_xor_sync(0x3u, acc, 1);
        if (d == 0) out[b] = acc + other + bmlp[0];
    }
}

// ============================================================
extern "C" void kernel_launch(void* const* d_in, const int* in_sizes, int n_in,
                              void* d_out, int out_size) {
    const float* x     = (const float*)d_in[0];
    const int*   ei    = (const int*)d_in[1];
    const float* ea    = (const float*)d_in[2];
    const float* Wrel  = (const float*)d_in[4];
    const float* brel  = (const float*)d_in[5];
    const float* Wroot = (const float*)d_in[6];

    // Resolve remaining indices by size (dict-order vs signature-order safe).
    int L = -1, iw = -1, ib = -1;
    for (int i = 0; i < n_in; i++) {
        if (in_sizes[i] == 24 && L < 0) L = i;       // w_ih_l0 starts contiguous LSTM block
        if (in_sizes[i] == 15000) iw = i;            // W_mlp
        if (in_sizes[i] == 1) ib = i;                // b_mlp
    }
    int E = in_sizes[2];

    cudaFuncSetAttribute(k_lstm, cudaFuncAttributeMaxDynamicSharedMemorySize, 160000);

    k_prep<<<1, 1024>>>(ei, ea, brel, E);
    k_reduce<<<dim3(63, 32), 128>>>(x);
    k_gemm<<<dim3(20, KSPLIT), 128>>>(Wrel, Wroot);
    k_lstm<<<32, 128, 160000>>>(
        (const float*)d_in[L + 0],  (const float*)d_in[L + 1],
        (const float*)d_in[L + 2],  (const float*)d_in[L + 3],
        (const float*)d_in[L + 4],  (const float*)d_in[L + 5],
        (const float*)d_in[L + 6],  (const float*)d_in[L + 7],
        (const float*)d_in[L + 8],  (const float*)d_in[L + 9],
        (const float*)d_in[L + 10], (const float*)d_in[L + 11],
        (const float*)d_in[L + 12], (const float*)d_in[L + 13],
        (const float*)d_in[L + 14], (const float*)d_in[L + 15],
        (const float*)d_in[iw], (const float*)d_in[ib], (float*)d_out);
}

// round 3
// speedup vs baseline: 2.0001x; 2.0001x over previous
#include <cuda_runtime.h>

#define F_IN  8064
#define F_OUT 5000
#define NG    32
#define NPG   32
#define TT    2500

// ---- device scratch (no allocations allowed) ----
__device__ float g_c[NG * NPG];
__device__ float g_A[NG * F_IN];
__device__ float g_S[NG * F_IN];
__device__ float g_pooled[NG * F_OUT];

// ============================================================
// K0: per-node outgoing edge-weight sums c_j, and init pooled = 32*b_rel
// ============================================================
__global__ void k_prep(const int* __restrict__ edge_index,
                       const float* __restrict__ edge_attr,
                       const float* __restrict__ b_rel, int E) {
    __shared__ float cs[NG * NPG];
    int tid = threadIdx.x;
    cs[tid] = 0.f;
    __syncthreads();
    for (int e = tid; e < E; e += 1024)
        atomicAdd(&cs[edge_index[e]], edge_attr[e]);  // src row of edge_index
    __syncthreads();
    g_c[tid] = cs[tid];
    for (int i = tid; i < NG * F_OUT; i += 1024)
        g_pooled[i] = 32.0f * b_rel[i % F_OUT];
}

// ============================================================
// K1: A[g,f] = sum_j c_j * x[g*32+j, f];  S[g,f] = sum_j x[g*32+j, f]
// ============================================================
__global__ void k_reduce(const float* __restrict__ x) {
    int g = blockIdx.y;
    int f = blockIdx.x * 128 + threadIdx.x;
    __shared__ float cs[NPG];
    if (threadIdx.x < NPG) cs[threadIdx.x] = g_c[g * NPG + threadIdx.x];
    __syncthreads();
    const float* xp = x + (size_t)(g * NPG) * F_IN + f;
    float a = 0.f, s = 0.f;
#pragma unroll
    for (int j = 0; j < NPG; j++) {
        float v = xp[(size_t)j * F_IN];
        a = fmaf(cs[j], v, a);
        s += v;
    }
    g_A[g * F_IN + f] = a;
    g_S[g * F_IN + f] = s;
}

// ============================================================
// K2: pooled[g,o] += sum_k A[g,k]*W_rel[o,k] + S[g,k]*W_root[o,k]
// ============================================================
#define KSPLIT 21
#define KRANGE 384
#define KT     128

__global__ void __launch_bounds__(128) k_gemm(const float* __restrict__ Wrel,
                                              const float* __restrict__ Wroot) {
    __shared__ float sA[32][KT];
    __shared__ float sS[32][KT];
    int tid = threadIdx.x;
    int oa = blockIdx.x * 256 + tid;
    int ob = oa + 128;
    bool vb = (ob < F_OUT);
    int obc = vb ? ob : oa;
    int k0 = blockIdx.y * KRANGE;

    float acc0[32], acc1[32];
#pragma unroll
    for (int g = 0; g < 32; g++) { acc0[g] = 0.f; acc1[g] = 0.f; }

    for (int ch = 0; ch < KRANGE / KT; ch++) {
        int kc = k0 + ch * KT;
        __syncthreads();
        for (int idx = tid; idx < 32 * KT; idx += 128) {
            int r = idx / KT, c = idx % KT;
            sA[r][c] = g_A[r * F_IN + kc + c];
            sS[r][c] = g_S[r * F_IN + kc + c];
        }
        __syncthreads();
        const float4* wra = (const float4*)(Wrel  + (size_t)oa  * F_IN + kc);
        const float4* wrb = (const float4*)(Wrel  + (size_t)obc * F_IN + kc);
        const float4* woa = (const float4*)(Wroot + (size_t)oa  * F_IN + kc);
        const float4* wob = (const float4*)(Wroot + (size_t)obc * F_IN + kc);
#pragma unroll 1
        for (int q = 0; q < KT / 4; q++) {
            float4 ra = wra[q], rb = wrb[q], ta = woa[q], tb = wob[q];
#pragma unroll
            for (int c = 0; c < 4; c++) {
                int k = q * 4 + c;
                float wr0 = (&ra.x)[c], wr1 = (&rb.x)[c];
                float wo0 = (&ta.x)[c], wo1 = (&tb.x)[c];
#pragma unroll
                for (int g = 0; g < 32; g++) {
                    float av = sA[g][k], sv = sS[g][k];
                    acc0[g] = fmaf(av, wr0, fmaf(sv, wo0, acc0[g]));
                    acc1[g] = fmaf(av, wr1, fmaf(sv, wo1, acc1[g]));
                }
            }
        }
    }
#pragma unroll
    for (int g = 0; g < 32; g++) {
        atomicAdd(&g_pooled[g * F_OUT + oa], acc0[g]);
        if (vb) atomicAdd(&g_pooled[g * F_OUT + ob], acc1[g]);
    }
}

// ============================================================
// K3: two BiLSTM layers (HID=3) + fused final MLP dot. One block per graph.
// 6 active lanes: lane = d*3 + j  (d: 0=fwd,1=bwd ; j: hidden unit).
// Each lane computes the 4 gates (i,f,g,o) of its unit; h broadcast via shfl.
// Activations use hardware tanh.approx (MUFU.TANH).
// smem: seq[5008] | o0[2500*8] | wm[15000]  -> 160,032 B dynamic
// ============================================================
__device__ __forceinline__ float tanh_fast(float x) {
    float r; asm("tanh.approx.f32 %0, %1;" : "=f"(r) : "f"(x)); return r;
}
__device__ __forceinline__ float sigm_fast(float x) {
    return fmaf(0.5f, tanh_fast(0.5f * x), 0.5f);
}

__global__ void __launch_bounds__(128) k_lstm(
    const float* __restrict__ wih0,  const float* __restrict__ whh0,
    const float* __restrict__ bih0,  const float* __restrict__ bhh0,
    const float* __restrict__ wih0r, const float* __restrict__ whh0r,
    const float* __restrict__ bih0r, const float* __restrict__ bhh0r,
    const float* __restrict__ wih1,  const float* __restrict__ whh1,
    const float* __restrict__ bih1,  const float* __restrict__ bhh1,
    const float* __restrict__ wih1r, const float* __restrict__ whh1r,
    const float* __restrict__ bih1r, const float* __restrict__ bhh1r,
    const float* __restrict__ wmlp,  const float* __restrict__ bmlp,
    float* __restrict__ out)
{
    extern __shared__ float sm[];
    float* seq = sm;              // 5000 (+8 pad)
    float* o0  = sm + 5008;       // 2500*8
    float* wm  = sm + 25008;      // 15000
    int b = blockIdx.x, tid = threadIdx.x;

    for (int i = tid; i < F_OUT; i += 128) seq[i] = g_pooled[b * F_OUT + i];
    for (int i = tid; i < 15000; i += 128) wm[i] = wmlp[i];
    __syncthreads();

    if (tid < 6) {
        const int d = tid / 3;       // direction
        const int j = tid % 3;       // hidden unit
        const int stp = d ? -1 : 1;
        const unsigned MASK = 0x3Fu;
        const int base = d * 3;

        // ---------------- Phase A: layer 0 ----------------
        {
            const float* WIH = d ? wih0r : wih0;
            const float* WHH = d ? whh0r : whh0;
            const float* BI  = d ? bih0r : bih0;
            const float* BH  = d ? bhh0r : bhh0;
            float wi[4][2], wh[4][3], bb[4];
#pragma unroll
            for (int g = 0; g < 4; g++) {
                int row = g * 3 + j;                       // i,f,g,o rows
                wi[g][0] = WIH[row * 2];
                wi[g][1] = WIH[row * 2 + 1];
                wh[g][0] = WHH[row * 3];
                wh[g][1] = WHH[row * 3 + 1];
                wh[g][2] = WHH[row * 3 + 2];
                bb[g] = BI[row] + BH[row];
            }
            float h0 = 0.f, h1 = 0.f, h2 = 0.f, c = 0.f;
            int t = d ? (TT - 1) : 0;
            float x0 = seq[2 * t], x1 = seq[2 * t + 1];
            for (int it = 0; it < TT; it++) {
                int tn = t + stp;
                int tc = min(max(tn, 0), TT - 1);
                float nx0 = seq[2 * tc], nx1 = seq[2 * tc + 1];   // prefetch

                float gv[4];
#pragma unroll
                for (int g = 0; g < 4; g++)
                    gv[g] = fmaf(x1, wi[g][1], fmaf(x0, wi[g][0], bb[g]));
#pragma unroll
                for (int g = 0; g < 4; g++)
                    gv[g] = fmaf(h2, wh[g][2],
                            fmaf(h1, wh[g][1], fmaf(h0, wh[g][0], gv[g])));

                c = fmaf(sigm_fast(gv[1]), c, sigm_fast(gv[0]) * tanh_fast(gv[2]));
                float h = sigm_fast(gv[3]) * tanh_fast(c);
                o0[t * 8 + base + j] = h;

                h0 = __shfl_sync(MASK, h, base + 0);
                h1 = __shfl_sync(MASK, h, base + 1);
                h2 = __shfl_sync(MASK, h, base + 2);
                t = tn; x0 = nx0; x1 = nx1;
            }
        }
        __syncwarp(MASK);   // o0 writes visible within the warp

        // ---------------- Phase B: layer 1 + fused MLP ----------------
        float acc = 0.f;
        {
            const float* WIH = d ? wih1r : wih1;
            const float* WHH = d ? whh1r : whh1;
            const float* BI  = d ? bih1r : bih1;
            const float* BH  = d ? bhh1r : bhh1;
            float wi[4][6], wh[4][3], bb[4];
#pragma unroll
            for (int g = 0; g < 4; g++) {
                int row = g * 3 + j;
#pragma unroll
                for (int m = 0; m < 6; m++) wi[g][m] = WIH[row * 6 + m];
                wh[g][0] = WHH[row * 3];
                wh[g][1] = WHH[row * 3 + 1];
                wh[g][2] = WHH[row * 3 + 2];
                bb[g] = BI[row] + BH[row];
            }
            float h0 = 0.f, h1 = 0.f, h2 = 0.f, c = 0.f;
            int t = d ? (TT - 1) : 0;
            float v[6];
#pragma unroll
            for (int m = 0; m < 6; m++) v[m] = o0[t * 8 + m];
            float wv = wm[t * 6 + base + j];

            for (int it = 0; it < TT; it++) {
                int tn = t + stp;
                int tc = min(max(tn, 0), TT - 1);
                float nv[6];
#pragma unroll
                for (int m = 0; m < 6; m++) nv[m] = o0[tc * 8 + m];   // prefetch
                float nwv = wm[tc * 6 + base + j];

                float gv[4];
#pragma unroll
                for (int g = 0; g < 4; g++) {
                    float s = bb[g];
#pragma unroll
                    for (int m = 0; m < 6; m++) s = fmaf(v[m], wi[g][m], s);
                    gv[g] = s;
                }
#pragma unroll
                for (int g = 0; g < 4; g++)
                    gv[g] = fmaf(h2, wh[g][2],
                            fmaf(h1, wh[g][1], fmaf(h0, wh[g][0], gv[g])));

                c = fmaf(sigm_fast(gv[1]), c, sigm_fast(gv[0]) * tanh_fast(gv[2]));
                float h = sigm_fast(gv[3]) * tanh_fast(c);
                acc = fmaf(h, wv, acc);

                h0 = __shfl_sync(MASK, h, base + 0);
                h1 = __shfl_sync(MASK, h, base + 1);
                h2 = __shfl_sync(MASK, h, base + 2);
                t = tn;
#pragma unroll
                for (int m = 0; m < 6; m++) v[m] = nv[m];
                wv = nwv;
            }
        }
        seq[tid] = acc;                 // seq no longer needed; reuse as scratch
        __syncwarp(MASK);
        if (tid == 0)
            out[b] = seq[0] + seq[1] + seq[2] + seq[3] + seq[4] + seq[5] + bmlp[0];
    }
}

// ============================================================
extern "C" void kernel_launch(void* const* d_in, const int* in_sizes, int n_in,
                              void* d_out, int out_size) {
    const float* x     = (const float*)d_in[0];
    const int*   ei    = (const int*)d_in[1];
    const float* ea    = (const float*)d_in[2];
    const float* Wrel  = (const float*)d_in[4];
    const float* brel  = (const float*)d_in[5];
    const float* Wroot = (const float*)d_in[6];

    // Resolve remaining indices by size (dict-order vs signature-order safe).
    int L = -1, iw = -1, ib = -1;
    for (int i = 0; i < n_in; i++) {
        if (in_sizes[i] == 24 && L < 0) L = i;       // w_ih_l0 starts contiguous LSTM block
        if (in_sizes[i] == 15000) iw = i;            // W_mlp
        if (in_sizes[i] == 1) ib = i;                // b_mlp
    }
    int E = in_sizes[2];

    cudaFuncSetAttribute(k_lstm, cudaFuncAttributeMaxDynamicSharedMemorySize, 160200);

    k_prep<<<1, 1024>>>(ei, ea, brel, E);
    k_reduce<<<dim3(63, 32), 128>>>(x);
    k_gemm<<<dim3(20, KSPLIT), 128>>>(Wrel, Wroot);
    k_lstm<<<32, 128, 160200>>>(
        (const float*)d_in[L + 0],  (const float*)d_in[L + 1],
        (const float*)d_in[L + 2],  (const float*)d_in[L + 3],
        (const float*)d_in[L + 4],  (const float*)d_in[L + 5],
        (const float*)d_in[L + 6],  (const float*)d_in[L + 7],
        (const float*)d_in[L + 8],  (const float*)d_in[L + 9],
        (const float*)d_in[L + 10], (const float*)d_in[L + 11],
        (const float*)d_in[L + 12], (const float*)d_in[L + 13],
        (const float*)d_in[L + 14], (const float*)d_in[L + 15],
        (const float*)d_in[iw], (const float*)d_in[ib], (float*)d_out);
}